// round 14
// baseline (speedup 1.0000x reference)
#include <cuda_runtime.h>
#include <cuda_fp16.h>
#include <cstdint>

#define SEQ   21
#define BDIM  8192
#define HDIM  1024
#define MTOT  (SEQ * BDIM)   // 172032

#define BM 128
#define BN 128
#define BK 64
#define NKT (HDIM / BK)      // 16
#define STAGES 3
#define ROWB 128                          // bytes per smem row (swizzled, no pad)
#define A_BYTES (BM * ROWB)               // 16384
#define B_BYTES (BN * ROWB)               // 16384
#define STAGE_BYTES (A_BYTES + B_BYTES)   // 32768
#define SMEM_SIZE (STAGES * STAGE_BYTES)  // 98304 (96 KB, 2 CTAs/SM fit)

#define NCHUNK 4

// SW128 swizzle: XOR bits[4:6] with row bits[7:9]
#define SWZ(x) ((x) ^ (((x) >> 3) & 0x70))

// ---- device scratch (allocation-free rule) ----
__device__ __half g_allh_h[(size_t)MTOT * HDIM];   // 352 MB fp16 copy of allh
__device__ __half g_c_h[(size_t)BDIM * HDIM];      // 16 MB fp16 copy of c
__device__ __half g_wt_h[(size_t)HDIM * HDIM];     // W^T fp16 [n][k]
__device__ __half g_vt_h[(size_t)HDIM * HDIM];     // V^T fp16 [n][k]
__device__ float  g_wc[(size_t)BDIM * HDIM];       // 32 MB: wc = c @ W (fp32)
__device__ float  g_scores[MTOT];

// ------------------------- helpers -------------------------
__device__ __forceinline__ uint32_t smem_u32(const void* p) {
    uint32_t a;
    asm("{ .reg .u64 t; cvta.to.shared.u64 t, %1; cvt.u32.u64 %0, t; }"
        : "=r"(a) : "l"(p));
    return a;
}
__device__ __forceinline__ float fast_tanh(float x) {
    float r; asm("tanh.approx.f32 %0, %1;" : "=f"(r) : "f"(x)); return r;
}
__device__ __forceinline__ uint32_t pack_half2(float lo, float hi) {
    uint32_t r;
    asm("cvt.rn.f16x2.f32 %0, %1, %2;" : "=r"(r) : "f"(hi), "f"(lo));
    return r;
}
__device__ __forceinline__ void cp_async16(uint32_t dst, const void* src) {
    asm volatile("cp.async.cg.shared.global [%0], [%1], 16;" :: "r"(dst), "l"(src));
}
__device__ __forceinline__ void cp_commit() {
    asm volatile("cp.async.commit_group;" ::: "memory");
}
template <int N>
__device__ __forceinline__ void cp_wait() {
    asm volatile("cp.async.wait_group %0;" :: "n"(N) : "memory");
}
__device__ __forceinline__ void ldsm4(uint32_t& r0, uint32_t& r1,
                                      uint32_t& r2, uint32_t& r3, uint32_t addr) {
    asm volatile("ldmatrix.sync.aligned.m8n8.x4.shared.b16 {%0,%1,%2,%3}, [%4];"
                 : "=r"(r0), "=r"(r1), "=r"(r2), "=r"(r3) : "r"(addr));
}
__device__ __forceinline__ void mma_f16(
    float& d0, float& d1, float& d2, float& d3,
    uint32_t a0, uint32_t a1, uint32_t a2, uint32_t a3,
    uint32_t b0, uint32_t b1)
{
    asm volatile(
        "mma.sync.aligned.m16n8k16.row.col.f32.f16.f16.f32 "
        "{%0,%1,%2,%3}, {%4,%5,%6,%7}, {%8,%9}, {%0,%1,%2,%3};\n"
        : "+f"(d0), "+f"(d1), "+f"(d2), "+f"(d3)
        : "r"(a0), "r"(a1), "r"(a2), "r"(a3), "r"(b0), "r"(b1));
}

// ------------------------- small kernels -------------------------
__global__ void zero_scores_kernel() {
    int i = blockIdx.x * blockDim.x + threadIdx.x;
    if (i < MTOT) g_scores[i] = 0.0f;
}

// f32 -> f16, exact grid, no loop: each thread converts 16 floats
// (4 x float4 loads, 2 x uint4 stores). grid*256*16 must equal element count.
__global__ __launch_bounds__(256)
void f32_to_f16_kernel(const float* __restrict__ in, __half* __restrict__ out) {
    size_t t4 = ((size_t)blockIdx.x * 256 + threadIdx.x) * 4;   // float4 index
    const float4* in4 = (const float4*)in;
    uint4* out4 = (uint4*)out;                                   // 8 halves each
    float4 v0 = in4[t4 + 0];
    float4 v1 = in4[t4 + 1];
    float4 v2 = in4[t4 + 2];
    float4 v3 = in4[t4 + 3];
    uint4 o0, o1;
    o0.x = pack_half2(v0.x, v0.y); o0.y = pack_half2(v0.z, v0.w);
    o0.z = pack_half2(v1.x, v1.y); o0.w = pack_half2(v1.z, v1.w);
    o1.x = pack_half2(v2.x, v2.y); o1.y = pack_half2(v2.z, v2.w);
    o1.z = pack_half2(v3.x, v3.y); o1.w = pack_half2(v3.z, v3.w);
    out4[(t4 >> 1) + 0] = o0;
    out4[(t4 >> 1) + 1] = o1;
}

__global__ void transpose_f16_kernel(const float* __restrict__ in,
                                     __half* __restrict__ out) {
    __shared__ float t[32][33];
    int x = blockIdx.x * 32 + threadIdx.x;
#pragma unroll
    for (int i = 0; i < 32; i += 8) {
        int y = blockIdx.y * 32 + threadIdx.y + i;
        t[threadIdx.y + i][threadIdx.x] = in[(size_t)y * HDIM + x];
    }
    __syncthreads();
    int x2 = blockIdx.y * 32 + threadIdx.x;
#pragma unroll
    for (int i = 0; i < 32; i += 8) {
        int y2 = blockIdx.x * 32 + threadIdx.y + i;
        out[(size_t)y2 * HDIM + x2] = __float2half(t[threadIdx.x][threadIdx.y + i]);
    }
}

// ---------------------------------------------------------------------------
// FP16 GEMM (fp32 accum). CTA tile 128x128, BK=64, swizzled 128B smem rows,
// 3-stage cp.async pipeline, 4 warps (2M x 2N), warp tile 64x64, 2 CTAs/SM.
// Staging: 8 lanes cover one full 128B row (coalesced).
//   A: [M][K] f16 row-major.  Bt: [N][K] f16 (transposed weight).
// Grid: (n_tiles, s_count, b_tiles); s = s0 + blockIdx.y; m0 = s*BDIM + bt*BM.
// MODE 0: C -> g_wc.
// MODE 1: e = tanh(C + wc[b,:] + bias[s,:]); scores[row] += e . Wt
// ---------------------------------------------------------------------------
template <int MODE>
__global__ __launch_bounds__(128, 2)
void gemm_f16_kernel(const __half* __restrict__ A,
                     const __half* __restrict__ Bt,
                     const float* __restrict__ bias,
                     const float* __restrict__ Wt,
                     int s0)
{
    extern __shared__ __align__(1024) char smem[];
    const uint32_t sbase = smem_u32(smem);

    const int tid   = threadIdx.x;
    const int lane  = tid & 31;
    const int wid   = tid >> 5;
    const int warpM = wid & 1;   // 0..1  (64-row bands)
    const int warpN = wid >> 1;  // 0..1  (64-col bands)
    const int grp   = lane >> 2; // 0..7
    const int qid   = lane & 3;  // 0..3

    const int sidx = s0 + blockIdx.y;
    const int m0 = sidx * BDIM + blockIdx.z * BM;
    const int n0 = blockIdx.x * BN;
    const __half* Ab = A  + (size_t)m0 * HDIM;
    const __half* Bb = Bt + (size_t)n0 * HDIM;

    // ldmatrix lane offsets (swizzled bytes within a stage).
    // kk-step offset (kk*32 bytes, bits 5-6) applied by XOR.
    uint32_t aoff[4], boff[4];
#pragma unroll
    for (int mt = 0; mt < 4; mt++) {
        uint32_t lin = (uint32_t)((warpM * 64 + mt * 16 + (lane & 15)) * ROWB
                                  + (lane >> 4) * 16);
        aoff[mt] = SWZ(lin);
    }
#pragma unroll
    for (int n2 = 0; n2 < 4; n2++) {
        uint32_t lin = (uint32_t)((warpN * 64 + n2 * 16 + (lane & 7)
                                   + (((lane >> 4) & 1) * 8)) * ROWB
                                  + ((lane >> 3) & 1) * 16);
        boff[n2] = A_BYTES + SWZ(lin);
    }

    float acc[4][8][4];
#pragma unroll
    for (int i = 0; i < 4; i++)
#pragma unroll
        for (int j = 0; j < 8; j++)
#pragma unroll
            for (int k = 0; k < 4; k++) acc[i][j][k] = 0.0f;

    // staging: 1024 16B-chunks per tile; 8 lanes per 128B row (coalesced)
    auto issue_tile = [&](int kt) {
        if (kt < NKT) {
            uint32_t soff = sbase + (uint32_t)(kt % STAGES) * STAGE_BYTES;
            int kb = kt * BK;
#pragma unroll
            for (int i = 0; i < 8; i++) {
                int id = tid + 128 * i;
                int r = id >> 3, cc = id & 7;
                uint32_t dst = (uint32_t)(r * ROWB + ((cc * 16) ^ ((r & 7) << 4)));
                cp_async16(soff + dst, Ab + (size_t)r * HDIM + kb + cc * 8);
            }
#pragma unroll
            for (int i = 0; i < 8; i++) {
                int id = tid + 128 * i;
                int r = id >> 3, cc = id & 7;
                uint32_t dst = (uint32_t)(r * ROWB + ((cc * 16) ^ ((r & 7) << 4)));
                cp_async16(soff + A_BYTES + dst, Bb + (size_t)r * HDIM + kb + cc * 8);
            }
        }
        cp_commit();
    };

    issue_tile(0);
    issue_tile(1);

    for (int kt = 0; kt < NKT; kt++) {
        cp_wait<STAGES - 2>();
        __syncthreads();
        issue_tile(kt + STAGES - 1);

        const uint32_t buf = sbase + (uint32_t)(kt % STAGES) * STAGE_BYTES;
#pragma unroll
        for (int kk = 0; kk < 4; kk++) {
            const uint32_t kx = (uint32_t)(kk * 32);
            uint32_t af[4][4], bf[8][2];
#pragma unroll
            for (int mt = 0; mt < 4; mt++)
                ldsm4(af[mt][0], af[mt][1], af[mt][2], af[mt][3],
                      buf + (aoff[mt] ^ kx));
#pragma unroll
            for (int n2 = 0; n2 < 4; n2++)
                ldsm4(bf[2 * n2][0], bf[2 * n2][1],
                      bf[2 * n2 + 1][0], bf[2 * n2 + 1][1],
                      buf + (boff[n2] ^ kx));
#pragma unroll
            for (int mt = 0; mt < 4; mt++)
#pragma unroll
                for (int nt = 0; nt < 8; nt++)
                    mma_f16(acc[mt][nt][0], acc[mt][nt][1],
                            acc[mt][nt][2], acc[mt][nt][3],
                            af[mt][0], af[mt][1], af[mt][2], af[mt][3],
                            bf[nt][0], bf[nt][1]);
        }
    }

    if (MODE == 0) {
#pragma unroll
        for (int mt = 0; mt < 4; mt++) {
            int r0 = m0 + warpM * 64 + mt * 16 + grp;
#pragma unroll
            for (int nt = 0; nt < 8; nt++) {
                int c0 = n0 + warpN * 64 + nt * 8 + qid * 2;
                *(float2*)&g_wc[(size_t)r0 * HDIM + c0] =
                    make_float2(acc[mt][nt][0], acc[mt][nt][1]);
                *(float2*)&g_wc[(size_t)(r0 + 8) * HDIM + c0] =
                    make_float2(acc[mt][nt][2], acc[mt][nt][3]);
            }
        }
    } else {
        float part[8];
#pragma unroll
        for (int i = 0; i < 8; i++) part[i] = 0.0f;

        const float* biasrow = bias + (size_t)sidx * HDIM;
        const int bbase = blockIdx.z * BM;

#pragma unroll
        for (int nt = 0; nt < 8; nt++) {
            int c0 = n0 + warpN * 64 + nt * 8 + qid * 2;
            float2 wt2 = *(const float2*)&Wt[c0];
            float2 bi2 = *(const float2*)&biasrow[c0];
#pragma unroll
            for (int mt = 0; mt < 4; mt++) {
                int b0 = bbase + warpM * 64 + mt * 16 + grp;
                float2 w0 = *(const float2*)&g_wc[(size_t)b0 * HDIM + c0];
                float2 w1 = *(const float2*)&g_wc[(size_t)(b0 + 8) * HDIM + c0];
                part[mt * 2]     += fast_tanh(acc[mt][nt][0] + w0.x + bi2.x) * wt2.x
                                  + fast_tanh(acc[mt][nt][1] + w0.y + bi2.y) * wt2.y;
                part[mt * 2 + 1] += fast_tanh(acc[mt][nt][2] + w1.x + bi2.x) * wt2.x
                                  + fast_tanh(acc[mt][nt][3] + w1.y + bi2.y) * wt2.y;
            }
        }
#pragma unroll
        for (int i = 0; i < 8; i++) {
            part[i] += __shfl_xor_sync(0xffffffffu, part[i], 1);
            part[i] += __shfl_xor_sync(0xffffffffu, part[i], 2);
        }
        if (qid == 0) {
#pragma unroll
            for (int mt = 0; mt < 4; mt++) {
                int r0 = m0 + warpM * 64 + mt * 16 + grp;
                atomicAdd(&g_scores[r0],     part[mt * 2]);
                atomicAdd(&g_scores[r0 + 8], part[mt * 2 + 1]);
            }
        }
    }
}

// ---------------------------------------------------------------------------
// Per-b softmax over SEQ scores + weighted sum of fp16 allh rows -> out[b, :]
// ---------------------------------------------------------------------------
__global__ __launch_bounds__(256)
void softmax_combine_kernel(float* __restrict__ out)
{
    int b = blockIdx.x;
    __shared__ float s_alpha[32];

    if (threadIdx.x < 32) {
        int lane = threadIdx.x;
        float v = (lane < SEQ) ? g_scores[lane * BDIM + b] : -1e30f;
        float m = v;
#pragma unroll
        for (int o = 16; o > 0; o >>= 1)
            m = fmaxf(m, __shfl_xor_sync(0xffffffffu, m, o));
        float e = (lane < SEQ) ? __expf(v - m) : 0.0f;
        float sum = e;
#pragma unroll
        for (int o = 16; o > 0; o >>= 1)
            sum += __shfl_xor_sync(0xffffffffu, sum, o);
        s_alpha[lane] = e / sum;
    }
    __syncthreads();

    const uint2* hb = (const uint2*)(g_allh_h + (size_t)b * HDIM) + threadIdx.x;
    float4 accv = make_float4(0.f, 0.f, 0.f, 0.f);
#pragma unroll
    for (int s = 0; s < SEQ; s++) {
        float a = s_alpha[s];
        uint2 v = hb[(size_t)s * (BDIM * HDIM / 4)];
        float2 f0 = __half22float2(*(__half2*)&v.x);
        float2 f1 = __half22float2(*(__half2*)&v.y);
        accv.x += a * f0.x; accv.y += a * f0.y;
        accv.z += a * f1.x; accv.w += a * f1.y;
    }
    ((float4*)(out + (size_t)b * HDIM))[threadIdx.x] = accv;
}

// ------------------------- launch -------------------------
extern "C" void kernel_launch(void* const* d_in, const int* in_sizes, int n_in,
                              void* d_out, int out_size)
{
    const float* c    = (const float*)d_in[0];  // [1, B, H]
    const float* allh = (const float*)d_in[1];  // [S, B, H]
    const float* W    = (const float*)d_in[2];  // [H, H]
    const float* V    = (const float*)d_in[3];  // [H, H]
    const float* bias = (const float*)d_in[4];  // [S, H]
    const float* Wt   = (const float*)d_in[5];  // [H, 1]
    float* out = (float*)d_out;                 // [1, B, H]
    (void)in_sizes; (void)n_in; (void)out_size;

    // chunk split over s: 5+5+5+6
    static const int s_begin[NCHUNK] = {0, 5, 10, 15};
    static const int s_count[NCHUNK] = {5, 5, 5, 6};

    // One-time setup (uncaptured correctness call). Resource footprint kept
    // identical to the passing round-12 version: ONE side stream, TWO events.
    static cudaStream_t s_conv = nullptr;
    static cudaEvent_t  e_fork = nullptr, e_conv = nullptr;
    if (!s_conv) {
        cudaFuncSetAttribute(gemm_f16_kernel<0>,
                             cudaFuncAttributeMaxDynamicSharedMemorySize, SMEM_SIZE);
        cudaFuncSetAttribute(gemm_f16_kernel<1>,
                             cudaFuncAttributeMaxDynamicSharedMemorySize, SMEM_SIZE);
        cudaStreamCreateWithFlags(&s_conv, cudaStreamNonBlocking);
        cudaEventCreateWithFlags(&e_fork, cudaEventDisableTiming);
        cudaEventCreateWithFlags(&e_conv, cudaEventDisableTiming);
    }

    __half* c_h;    cudaGetSymbolAddress((void**)&c_h,    g_c_h);
    __half* allh_h; cudaGetSymbolAddress((void**)&allh_h, g_allh_h);
    __half* wt_h;   cudaGetSymbolAddress((void**)&wt_h,   g_wt_h);
    __half* vt_h;   cudaGetSymbolAddress((void**)&vt_h,   g_vt_h);

    // Fork the conversion stream off the main stream.
    cudaEventRecord(e_fork, 0);
    cudaStreamWaitEvent(s_conv, e_fork, 0);

    // Main-stream prologue (independent of allh conversion).
    zero_scores_kernel<<<MTOT / 256, 256>>>();
    transpose_f16_kernel<<<dim3(32, 32), dim3(32, 8)>>>(W, wt_h);
    transpose_f16_kernel<<<dim3(32, 32), dim3(32, 8)>>>(V, vt_h);
    f32_to_f16_kernel<<<BDIM * HDIM / 4096, 256>>>(c, c_h);
    gemm_f16_kernel<0><<<dim3(HDIM / BN, 1, BDIM / BM), 128, SMEM_SIZE>>>(
        c_h, wt_h, nullptr, nullptr, 0);

    // Pipelined: conv chunk i on s_conv -> record e_conv -> main stream waits
    // and runs gemm chunk i. Re-recording the single event is capture-legal:
    // each wait binds to the most recent record at enqueue time.
    for (int i = 0; i < NCHUNK; i++) {
        size_t off = (size_t)s_begin[i] * BDIM * HDIM;
        int blocks = s_count[i] * (BDIM * HDIM / 4096);
        f32_to_f16_kernel<<<blocks, 256, 0, s_conv>>>(allh + off, allh_h + off);
        cudaEventRecord(e_conv, s_conv);
        cudaStreamWaitEvent(0, e_conv, 0);
        gemm_f16_kernel<1><<<dim3(HDIM / BN, s_count[i], BDIM / BM),
                             128, SMEM_SIZE>>>(
            allh_h, vt_h, bias, Wt, s_begin[i]);
    }

    // Softmax + combine on main stream (ordered after all gemm chunks).
    softmax_combine_kernel<<<BDIM, 256>>>(out);
}

// round 15
// speedup vs baseline: 1.0620x; 1.0620x over previous
#include <cuda_runtime.h>
#include <cuda_fp16.h>
#include <cstdint>

#define SEQ   21
#define BDIM  8192
#define HDIM  1024
#define MTOT  (SEQ * BDIM)   // 172032

#define BM 128
#define BN 128
#define BK 64
#define NKT (HDIM / BK)      // 16
#define STAGES 3
#define ROWB 128                          // bytes per smem row (swizzled, no pad)
#define A_BYTES (BM * ROWB)               // 16384
#define B_BYTES (BN * ROWB)               // 16384
#define STAGE_BYTES (A_BYTES + B_BYTES)   // 32768
#define SMEM_SIZE (STAGES * STAGE_BYTES)  // 98304 (96 KB, 2 CTAs/SM fit)

// SW128 swizzle: XOR bits[4:6] with row bits[7:9]
#define SWZ(x) ((x) ^ (((x) >> 3) & 0x70))

// ---- device scratch (allocation-free rule) ----
__device__ __half g_allh_h[(size_t)MTOT * HDIM];   // 352 MB fp16 copy of allh
__device__ __half g_c_h[(size_t)BDIM * HDIM];      // 16 MB fp16 copy of c
__device__ __half g_wt_h[(size_t)HDIM * HDIM];     // W^T fp16 [n][k]
__device__ __half g_vt_h[(size_t)HDIM * HDIM];     // V^T fp16 [n][k]
__device__ __half g_wc_h[(size_t)BDIM * HDIM];     // 16 MB: wc = c @ W (fp16)
__device__ float  g_scores[MTOT];

// ------------------------- helpers -------------------------
__device__ __forceinline__ uint32_t smem_u32(const void* p) {
    uint32_t a;
    asm("{ .reg .u64 t; cvta.to.shared.u64 t, %1; cvt.u32.u64 %0, t; }"
        : "=r"(a) : "l"(p));
    return a;
}
__device__ __forceinline__ float fast_tanh(float x) {
    float r; asm("tanh.approx.f32 %0, %1;" : "=f"(r) : "f"(x)); return r;
}
__device__ __forceinline__ uint32_t pack_half2(float lo, float hi) {
    uint32_t r;
    asm("cvt.rn.f16x2.f32 %0, %1, %2;" : "=r"(r) : "f"(hi), "f"(lo));
    return r;
}
__device__ __forceinline__ void cp_async16(uint32_t dst, const void* src) {
    asm volatile("cp.async.cg.shared.global [%0], [%1], 16;" :: "r"(dst), "l"(src));
}
__device__ __forceinline__ void cp_commit() {
    asm volatile("cp.async.commit_group;" ::: "memory");
}
template <int N>
__device__ __forceinline__ void cp_wait() {
    asm volatile("cp.async.wait_group %0;" :: "n"(N) : "memory");
}
__device__ __forceinline__ void ldsm4(uint32_t& r0, uint32_t& r1,
                                      uint32_t& r2, uint32_t& r3, uint32_t addr) {
    asm volatile("ldmatrix.sync.aligned.m8n8.x4.shared.b16 {%0,%1,%2,%3}, [%4];"
                 : "=r"(r0), "=r"(r1), "=r"(r2), "=r"(r3) : "r"(addr));
}
__device__ __forceinline__ void mma_f16(
    float& d0, float& d1, float& d2, float& d3,
    uint32_t a0, uint32_t a1, uint32_t a2, uint32_t a3,
    uint32_t b0, uint32_t b1)
{
    asm volatile(
        "mma.sync.aligned.m16n8k16.row.col.f32.f16.f16.f32 "
        "{%0,%1,%2,%3}, {%4,%5,%6,%7}, {%8,%9}, {%0,%1,%2,%3};\n"
        : "+f"(d0), "+f"(d1), "+f"(d2), "+f"(d3)
        : "r"(a0), "r"(a1), "r"(a2), "r"(a3), "r"(b0), "r"(b1));
}

// ------------------------- small kernels -------------------------
__global__ void zero_scores_kernel() {
    int i = blockIdx.x * blockDim.x + threadIdx.x;
    if (i < MTOT) g_scores[i] = 0.0f;
}

// f32 -> f16, exact grid, no loop: each thread converts 16 floats
// (4 x float4 loads, 2 x uint4 stores). grid*256*16 must equal element count.
__global__ __launch_bounds__(256)
void f32_to_f16_kernel(const float* __restrict__ in, __half* __restrict__ out) {
    size_t t4 = ((size_t)blockIdx.x * 256 + threadIdx.x) * 4;   // float4 index
    const float4* in4 = (const float4*)in;
    uint4* out4 = (uint4*)out;                                   // 8 halves each
    float4 v0 = in4[t4 + 0];
    float4 v1 = in4[t4 + 1];
    float4 v2 = in4[t4 + 2];
    float4 v3 = in4[t4 + 3];
    uint4 o0, o1;
    o0.x = pack_half2(v0.x, v0.y); o0.y = pack_half2(v0.z, v0.w);
    o0.z = pack_half2(v1.x, v1.y); o0.w = pack_half2(v1.z, v1.w);
    o1.x = pack_half2(v2.x, v2.y); o1.y = pack_half2(v2.z, v2.w);
    o1.z = pack_half2(v3.x, v3.y); o1.w = pack_half2(v3.z, v3.w);
    out4[(t4 >> 1) + 0] = o0;
    out4[(t4 >> 1) + 1] = o1;
}

__global__ void transpose_f16_kernel(const float* __restrict__ in,
                                     __half* __restrict__ out) {
    __shared__ float t[32][33];
    int x = blockIdx.x * 32 + threadIdx.x;
#pragma unroll
    for (int i = 0; i < 32; i += 8) {
        int y = blockIdx.y * 32 + threadIdx.y + i;
        t[threadIdx.y + i][threadIdx.x] = in[(size_t)y * HDIM + x];
    }
    __syncthreads();
    int x2 = blockIdx.y * 32 + threadIdx.x;
#pragma unroll
    for (int i = 0; i < 32; i += 8) {
        int y2 = blockIdx.x * 32 + threadIdx.y + i;
        out[(size_t)y2 * HDIM + x2] = __float2half(t[threadIdx.x][threadIdx.y + i]);
    }
}

// ---------------------------------------------------------------------------
// FP16 GEMM (fp32 accum). CTA tile 128x128, BK=64, swizzled 128B smem rows,
// 3-stage cp.async pipeline, 4 warps (2M x 2N), warp tile 64x64, 2 CTAs/SM.
// Staging: 8 lanes cover one full 128B row (coalesced).
//   A: [M][K] f16 row-major.  Bt: [N][K] f16 (transposed weight).
// Grid: (n_tiles, s, b_tiles); m0 = s*BDIM + bt*BM.
// MODE 0: C -> g_wc_h (fp16).
// MODE 1: e = tanh(C + wc[b,:] + bias[s,:]); scores[row] += e . Wt
// ---------------------------------------------------------------------------
template <int MODE>
__global__ __launch_bounds__(128, 2)
void gemm_f16_kernel(const __half* __restrict__ A,
                     const __half* __restrict__ Bt,
                     const float* __restrict__ bias,
                     const float* __restrict__ Wt)
{
    extern __shared__ __align__(1024) char smem[];
    const uint32_t sbase = smem_u32(smem);

    const int tid   = threadIdx.x;
    const int lane  = tid & 31;
    const int wid   = tid >> 5;
    const int warpM = wid & 1;   // 0..1  (64-row bands)
    const int warpN = wid >> 1;  // 0..1  (64-col bands)
    const int grp   = lane >> 2; // 0..7
    const int qid   = lane & 3;  // 0..3

    const int m0 = blockIdx.y * BDIM + blockIdx.z * BM;
    const int n0 = blockIdx.x * BN;
    const __half* Ab = A  + (size_t)m0 * HDIM;
    const __half* Bb = Bt + (size_t)n0 * HDIM;

    // ldmatrix lane offsets (swizzled bytes within a stage).
    // kk-step offset (kk*32 bytes, bits 5-6) applied by XOR.
    uint32_t aoff[4], boff[4];
#pragma unroll
    for (int mt = 0; mt < 4; mt++) {
        uint32_t lin = (uint32_t)((warpM * 64 + mt * 16 + (lane & 15)) * ROWB
                                  + (lane >> 4) * 16);
        aoff[mt] = SWZ(lin);
    }
#pragma unroll
    for (int n2 = 0; n2 < 4; n2++) {
        uint32_t lin = (uint32_t)((warpN * 64 + n2 * 16 + (lane & 7)
                                   + (((lane >> 4) & 1) * 8)) * ROWB
                                  + ((lane >> 3) & 1) * 16);
        boff[n2] = A_BYTES + SWZ(lin);
    }

    float acc[4][8][4];
#pragma unroll
    for (int i = 0; i < 4; i++)
#pragma unroll
        for (int j = 0; j < 8; j++)
#pragma unroll
            for (int k = 0; k < 4; k++) acc[i][j][k] = 0.0f;

    // staging: 1024 16B-chunks per tile; 8 lanes per 128B row (coalesced)
    auto issue_tile = [&](int kt) {
        if (kt < NKT) {
            uint32_t soff = sbase + (uint32_t)(kt % STAGES) * STAGE_BYTES;
            int kb = kt * BK;
#pragma unroll
            for (int i = 0; i < 8; i++) {
                int id = tid + 128 * i;
                int r = id >> 3, cc = id & 7;
                uint32_t dst = (uint32_t)(r * ROWB + ((cc * 16) ^ ((r & 7) << 4)));
                cp_async16(soff + dst, Ab + (size_t)r * HDIM + kb + cc * 8);
            }
#pragma unroll
            for (int i = 0; i < 8; i++) {
                int id = tid + 128 * i;
                int r = id >> 3, cc = id & 7;
                uint32_t dst = (uint32_t)(r * ROWB + ((cc * 16) ^ ((r & 7) << 4)));
                cp_async16(soff + A_BYTES + dst, Bb + (size_t)r * HDIM + kb + cc * 8);
            }
        }
        cp_commit();
    };

    issue_tile(0);
    issue_tile(1);

    for (int kt = 0; kt < NKT; kt++) {
        cp_wait<STAGES - 2>();
        __syncthreads();
        issue_tile(kt + STAGES - 1);

        const uint32_t buf = sbase + (uint32_t)(kt % STAGES) * STAGE_BYTES;
#pragma unroll
        for (int kk = 0; kk < 4; kk++) {
            const uint32_t kx = (uint32_t)(kk * 32);
            uint32_t af[4][4], bf[8][2];
#pragma unroll
            for (int mt = 0; mt < 4; mt++)
                ldsm4(af[mt][0], af[mt][1], af[mt][2], af[mt][3],
                      buf + (aoff[mt] ^ kx));
#pragma unroll
            for (int n2 = 0; n2 < 4; n2++)
                ldsm4(bf[2 * n2][0], bf[2 * n2][1],
                      bf[2 * n2 + 1][0], bf[2 * n2 + 1][1],
                      buf + (boff[n2] ^ kx));
#pragma unroll
            for (int mt = 0; mt < 4; mt++)
#pragma unroll
                for (int nt = 0; nt < 8; nt++)
                    mma_f16(acc[mt][nt][0], acc[mt][nt][1],
                            acc[mt][nt][2], acc[mt][nt][3],
                            af[mt][0], af[mt][1], af[mt][2], af[mt][3],
                            bf[nt][0], bf[nt][1]);
        }
    }

    if (MODE == 0) {
        // store wc tile as fp16 (halves store traffic + epilogue read traffic)
#pragma unroll
        for (int mt = 0; mt < 4; mt++) {
            int r0 = m0 + warpM * 64 + mt * 16 + grp;
#pragma unroll
            for (int nt = 0; nt < 8; nt++) {
                int c0 = n0 + warpN * 64 + nt * 8 + qid * 2;
                *(uint32_t*)&g_wc_h[(size_t)r0 * HDIM + c0] =
                    pack_half2(acc[mt][nt][0], acc[mt][nt][1]);
                *(uint32_t*)&g_wc_h[(size_t)(r0 + 8) * HDIM + c0] =
                    pack_half2(acc[mt][nt][2], acc[mt][nt][3]);
            }
        }
    } else {
        float part[8];
#pragma unroll
        for (int i = 0; i < 8; i++) part[i] = 0.0f;

        const float* biasrow = bias + (size_t)blockIdx.y * HDIM;
        const int bbase = blockIdx.z * BM;

#pragma unroll
        for (int nt = 0; nt < 8; nt++) {
            int c0 = n0 + warpN * 64 + nt * 8 + qid * 2;
            float2 wt2 = *(const float2*)&Wt[c0];
            float2 bi2 = *(const float2*)&biasrow[c0];
#pragma unroll
            for (int mt = 0; mt < 4; mt++) {
                int b0 = bbase + warpM * 64 + mt * 16 + grp;
                uint32_t w0u = *(const uint32_t*)&g_wc_h[(size_t)b0 * HDIM + c0];
                uint32_t w1u = *(const uint32_t*)&g_wc_h[(size_t)(b0 + 8) * HDIM + c0];
                float2 w0 = __half22float2(*(__half2*)&w0u);
                float2 w1 = __half22float2(*(__half2*)&w1u);
                part[mt * 2]     += fast_tanh(acc[mt][nt][0] + w0.x + bi2.x) * wt2.x
                                  + fast_tanh(acc[mt][nt][1] + w0.y + bi2.y) * wt2.y;
                part[mt * 2 + 1] += fast_tanh(acc[mt][nt][2] + w1.x + bi2.x) * wt2.x
                                  + fast_tanh(acc[mt][nt][3] + w1.y + bi2.y) * wt2.y;
            }
        }
#pragma unroll
        for (int i = 0; i < 8; i++) {
            part[i] += __shfl_xor_sync(0xffffffffu, part[i], 1);
            part[i] += __shfl_xor_sync(0xffffffffu, part[i], 2);
        }
        if (qid == 0) {
#pragma unroll
            for (int mt = 0; mt < 4; mt++) {
                int r0 = m0 + warpM * 64 + mt * 16 + grp;
                atomicAdd(&g_scores[r0],     part[mt * 2]);
                atomicAdd(&g_scores[r0 + 8], part[mt * 2 + 1]);
            }
        }
    }
}

// ---------------------------------------------------------------------------
// Per-b softmax over SEQ scores + weighted sum of fp16 allh rows -> out[b, :]
// ---------------------------------------------------------------------------
__global__ __launch_bounds__(256)
void softmax_combine_kernel(float* __restrict__ out)
{
    int b = blockIdx.x;
    __shared__ float s_alpha[32];

    if (threadIdx.x < 32) {
        int lane = threadIdx.x;
        float v = (lane < SEQ) ? g_scores[lane * BDIM + b] : -1e30f;
        float m = v;
#pragma unroll
        for (int o = 16; o > 0; o >>= 1)
            m = fmaxf(m, __shfl_xor_sync(0xffffffffu, m, o));
        float e = (lane < SEQ) ? __expf(v - m) : 0.0f;
        float sum = e;
#pragma unroll
        for (int o = 16; o > 0; o >>= 1)
            sum += __shfl_xor_sync(0xffffffffu, sum, o);
        s_alpha[lane] = e / sum;
    }
    __syncthreads();

    const uint2* hb = (const uint2*)(g_allh_h + (size_t)b * HDIM) + threadIdx.x;
    float4 accv = make_float4(0.f, 0.f, 0.f, 0.f);
#pragma unroll
    for (int s = 0; s < SEQ; s++) {
        float a = s_alpha[s];
        uint2 v = hb[(size_t)s * (BDIM * HDIM / 4)];
        float2 f0 = __half22float2(*(__half2*)&v.x);
        float2 f1 = __half22float2(*(__half2*)&v.y);
        accv.x += a * f0.x; accv.y += a * f0.y;
        accv.z += a * f1.x; accv.w += a * f1.y;
    }
    ((float4*)(out + (size_t)b * HDIM))[threadIdx.x] = accv;
}

// ------------------------- launch -------------------------
extern "C" void kernel_launch(void* const* d_in, const int* in_sizes, int n_in,
                              void* d_out, int out_size)
{
    const float* c    = (const float*)d_in[0];  // [1, B, H]
    const float* allh = (const float*)d_in[1];  // [S, B, H]
    const float* W    = (const float*)d_in[2];  // [H, H]
    const float* V    = (const float*)d_in[3];  // [H, H]
    const float* bias = (const float*)d_in[4];  // [S, H]
    const float* Wt   = (const float*)d_in[5];  // [H, 1]
    float* out = (float*)d_out;                 // [1, B, H]
    (void)in_sizes; (void)n_in; (void)out_size;

    // One-time setup on the (uncaptured) correctness call: smem attrs,
    // side stream + fork/join events for multi-stream graph capture.
    static cudaStream_t s_conv = nullptr;
    static cudaEvent_t  e_fork = nullptr, e_join = nullptr;
    if (!s_conv) {
        cudaFuncSetAttribute(gemm_f16_kernel<0>,
                             cudaFuncAttributeMaxDynamicSharedMemorySize, SMEM_SIZE);
        cudaFuncSetAttribute(gemm_f16_kernel<1>,
                             cudaFuncAttributeMaxDynamicSharedMemorySize, SMEM_SIZE);
        cudaStreamCreateWithFlags(&s_conv, cudaStreamNonBlocking);
        cudaEventCreateWithFlags(&e_fork, cudaEventDisableTiming);
        cudaEventCreateWithFlags(&e_join, cudaEventDisableTiming);
    }

    __half* c_h;    cudaGetSymbolAddress((void**)&c_h,    g_c_h);
    __half* allh_h; cudaGetSymbolAddress((void**)&allh_h, g_allh_h);
    __half* wt_h;   cudaGetSymbolAddress((void**)&wt_h,   g_wt_h);
    __half* vt_h;   cudaGetSymbolAddress((void**)&vt_h,   g_vt_h);

    // Fork: big allh f32->f16 conversion runs on the side stream, overlapped
    // with the main-stream prologue (zero/transposes/c-conversion/wc GEMM).
    cudaEventRecord(e_fork, 0);
    cudaStreamWaitEvent(s_conv, e_fork, 0);
    f32_to_f16_kernel<<<(int)((size_t)MTOT * HDIM / 4096), 256, 0, s_conv>>>(
        allh, allh_h);                              // 43008 blocks
    cudaEventRecord(e_join, s_conv);

    // Main-stream prologue
    zero_scores_kernel<<<MTOT / 256, 256>>>();
    transpose_f16_kernel<<<dim3(32, 32), dim3(32, 8)>>>(W, wt_h);
    transpose_f16_kernel<<<dim3(32, 32), dim3(32, 8)>>>(V, vt_h);
    f32_to_f16_kernel<<<BDIM * HDIM / 4096, 256>>>(c, c_h);   // 2048 blocks

    // wc = c @ W   (grid: n-tiles x 1 x b-tiles)
    gemm_f16_kernel<0><<<dim3(HDIM / BN, 1, BDIM / BM), 128, SMEM_SIZE>>>(
        c_h, wt_h, nullptr, nullptr);

    // Join: gemm1 needs the fp16 allh
    cudaStreamWaitEvent(0, e_join, 0);

    // fused vh GEMM + tanh + score reduction (grid: n-tiles x s x b-tiles)
    gemm_f16_kernel<1><<<dim3(HDIM / BN, SEQ, BDIM / BM), 128, SMEM_SIZE>>>(
        allh_h, vt_h, bias, Wt);

    // softmax over S and weighted combine
    softmax_combine_kernel<<<BDIM, 256>>>(out);
}